// round 5
// baseline (speedup 1.0000x reference)
#include <cuda_runtime.h>

#define BB 256
#define TT 2048
#define HH 128
#define FC1N 64
#define RING 32
#define RPAD 132    // ring row stride (16B-aligned; FC reads 4-way conflict)

// dynamic SMEM layout (float offsets); [0]=row A, [1]=row B where applicable
#define OFF_X     0                           // 2 * TT*3
#define OFF_R     (2 * TT * 3)                // 2 * RING*RPAD
#define OFF_WC    (OFF_R + 2 * RING * RPAD)   // [3][HH]
#define OFF_P     (OFF_WC + 3 * HH)           // 2 * [4][96]
#define OFF_BC    (OFF_P + 2 * 4 * 96)
#define SMEM_FLOATS (OFF_BC + 4)

__device__ __forceinline__ unsigned long long fma2(unsigned long long a,
                                                   unsigned long long b,
                                                   unsigned long long c) {
    unsigned long long d;
    asm("fma.rn.f32x2 %0, %1, %2, %3;" : "=l"(d) : "l"(a), "l"(b), "l"(c));
    return d;
}
__device__ __forceinline__ unsigned long long add2(unsigned long long a,
                                                   unsigned long long b) {
    unsigned long long d;
    asm("add.rn.f32x2 %0, %1, %2;" : "=l"(d) : "l"(a), "l"(b));
    return d;
}
__device__ __forceinline__ float2 unpack2(unsigned long long v) {
    float2 r;
    asm("mov.b64 {%0, %1}, %2;" : "=f"(r.x), "=f"(r.y) : "l"(v));
    return r;
}
__device__ __forceinline__ float tanh_fast(float x) {
    float y;
    asm("tanh.approx.f32 %0, %1;" : "=f"(y) : "f"(x));
    return y;
}
__device__ __forceinline__ void bar_row(int id) {
    asm volatile("bar.sync %0, 128;" :: "r"(id) : "memory");
}

__global__ __launch_bounds__(256, 1)
void rnn_rows2_kernel(const float* __restrict__ x,
                      const float* __restrict__ hidden,
                      const float* __restrict__ W_ih,
                      const float* __restrict__ W_hh,
                      const float* __restrict__ b_ih,
                      const float* __restrict__ b_hh,
                      const float* __restrict__ W_fc1,
                      const float* __restrict__ b_fc1,
                      const float* __restrict__ W_fc2,
                      const float* __restrict__ b_fc2,
                      float* __restrict__ out)
{
    extern __shared__ __align__(16) float sm[];

    const int tid = threadIdx.x;
    const int row = tid >> 7;           // 0: warps 0-3, 1: warps 4-7
    const int j   = tid & 127;          // hidden unit within row
    const int bid = row + 1;            // named barrier id for this row
    const int r   = 2 * blockIdx.x + row;   // global batch row

    float* xR   = sm + OFF_X + row * (TT * 3);
    float* ring = sm + OFF_R + row * (RING * RPAD);
    float* wc   = sm + OFF_WC;
    float* pr   = sm + OFF_P + row * (4 * 96);
    float* bc   = sm + OFF_BC;

    // ---- preload this row's x (128 threads per row, coalesced float4) ----
    {
        const float4* g = (const float4*)(x + (size_t)r * TT * 3);
        float4* s = (float4*)xR;
        #pragma unroll
        for (int i = 0; i < (TT * 3 / 4) / 128; i++)     // 12 iters
            s[i * 128 + j] = g[i * 128 + j];
    }

    // ---- W_hh row j as packed f32x2 (64 ull regs, same for both rows) ----
    unsigned long long w[HH / 2];
    {
        const unsigned long long* wg = (const unsigned long long*)(W_hh + j * HH);
        #pragma unroll
        for (int i = 0; i < HH / 2; i++) w[i] = wg[i];
    }

    const float wih0 = W_ih[j * 3 + 0];
    const float wih1 = W_ih[j * 3 + 1];
    const float wih2 = W_ih[j * 3 + 2];
    const float bias = b_ih[j] + b_hh[j];

    // ---- collapsed FC head (row 0 threads compute; both rows read) ----
    if (row == 0) {
        float c0 = 0.f, c1 = 0.f, c2 = 0.f;
        #pragma unroll 4
        for (int f = 0; f < FC1N; f++) {
            float v = W_fc1[f * HH + j];
            c0 = fmaf(W_fc2[0 * FC1N + f], v, c0);
            c1 = fmaf(W_fc2[1 * FC1N + f], v, c1);
            c2 = fmaf(W_fc2[2 * FC1N + f], v, c2);
        }
        wc[0 * HH + j] = c0; wc[1 * HH + j] = c1; wc[2 * HH + j] = c2;
        if (j < 3) {
            float s = 0.f;
            #pragma unroll 8
            for (int f = 0; f < FC1N; f++)
                s = fmaf(W_fc2[j * FC1N + f], b_fc1[f], s);
            bc[j] = s + b_fc2[j];
        }
    }

    // initial hidden state in slot RING-1 (t = -1)
    ring[(RING - 1) * RPAD + j] = hidden[r * HH + j];
    __syncthreads();     // one global barrier at init; rows decouple after this

    const int kg = j >> 5;     // FC k-group
    const int tl = j & 31;     // FC local timestep
    float* outr = out + (size_t)r * TT * 3;

    float hv = 0.f;

    for (int tc = 0; tc < TT / RING; tc++) {
        #pragma unroll 1
        for (int ts = 0; ts < RING; ts++) {
            const int t = tc * RING + ts;

            // x projection (independent of h)
            const float xv0 = xR[3 * t + 0];
            const float xv1 = xR[3 * t + 1];
            const float xv2 = xR[3 * t + 2];
            float xp = fmaf(xv2, wih2, fmaf(xv1, wih1, fmaf(xv0, wih0, bias)));

            // 128-wide dot(W_j, h_prev): 4 chains x 16 packed FMAs
            const ulonglong2* hp =
                (const ulonglong2*)(ring + ((ts - 1) & (RING - 1)) * RPAD);
            unsigned long long a0 = 0ull, a1 = 0ull, a2 = 0ull, a3 = 0ull;
            #pragma unroll
            for (int i = 0; i < 16; i++) {
                ulonglong2 ha = hp[2 * i];
                ulonglong2 hb = hp[2 * i + 1];
                a0 = fma2(w[4 * i + 0], ha.x, a0);
                a1 = fma2(w[4 * i + 1], ha.y, a1);
                a2 = fma2(w[4 * i + 2], hb.x, a2);
                a3 = fma2(w[4 * i + 3], hb.y, a3);
            }
            unsigned long long s2 = add2(add2(a0, a1), add2(a2, a3));
            float2 f = unpack2(s2);

            hv = tanh_fast(xp + (f.x + f.y));
            ring[ts * RPAD + j] = hv;
            bar_row(bid);               // syncs only this row's 4 warps
        }

        // ---- amortized FC drain for this row (slots 0..31) ----
        {
            const float4* w0 = (const float4*)(wc + 0 * HH + kg * 32);
            const float4* w1 = (const float4*)(wc + 1 * HH + kg * 32);
            const float4* w2 = (const float4*)(wc + 2 * HH + kg * 32);
            const float4* h4 = (const float4*)(ring + tl * RPAD + kg * 32);
            float p0 = 0.f, p1 = 0.f, p2 = 0.f;
            #pragma unroll
            for (int i = 0; i < 8; i++) {
                float4 v = h4[i];
                float4 u0 = w0[i], u1 = w1[i], u2 = w2[i];
                p0 = fmaf(v.x, u0.x, fmaf(v.y, u0.y, fmaf(v.z, u0.z, fmaf(v.w, u0.w, p0))));
                p1 = fmaf(v.x, u1.x, fmaf(v.y, u1.y, fmaf(v.z, u1.z, fmaf(v.w, u1.w, p1))));
                p2 = fmaf(v.x, u2.x, fmaf(v.y, u2.y, fmaf(v.z, u2.z, fmaf(v.w, u2.w, p2))));
            }
            pr[kg * 96 + tl * 3 + 0] = p0;
            pr[kg * 96 + tl * 3 + 1] = p1;
            pr[kg * 96 + tl * 3 + 2] = p2;
            bar_row(bid);

            if (j < 96) {
                float v = pr[j] + pr[96 + j] + pr[192 + j] + pr[288 + j] + bc[j % 3];
                outr[(size_t)(tc * RING) * 3 + j] = v;
            }
            // ring slot 0 is rewritten only after the next step's bar; partials
            // are rewritten only after 32 more barriers — no extra sync needed.
        }
    }

    // final hidden state
    out[(size_t)BB * TT * 3 + r * HH + j] = hv;
}

extern "C" void kernel_launch(void* const* d_in, const int* in_sizes, int n_in,
                              void* d_out, int out_size) {
    const float* x      = (const float*)d_in[0];
    const float* hidden = (const float*)d_in[1];
    const float* W_ih   = (const float*)d_in[2];
    const float* W_hh   = (const float*)d_in[3];
    const float* b_ih   = (const float*)d_in[4];
    const float* b_hh   = (const float*)d_in[5];
    const float* W_fc1  = (const float*)d_in[6];
    const float* b_fc1  = (const float*)d_in[7];
    const float* W_fc2  = (const float*)d_in[8];
    const float* b_fc2  = (const float*)d_in[9];
    float* out = (float*)d_out;

    const int smem_bytes = SMEM_FLOATS * sizeof(float);
    static bool attr_set = false;
    if (!attr_set) {
        cudaFuncSetAttribute(rnn_rows2_kernel,
                             cudaFuncAttributeMaxDynamicSharedMemorySize,
                             smem_bytes);
        attr_set = true;
    }
    rnn_rows2_kernel<<<BB / 2, 256, smem_bytes>>>(
        x, hidden, W_ih, W_hh, b_ih, b_hh,
        W_fc1, b_fc1, W_fc2, b_fc2, out);
}

// round 6
// speedup vs baseline: 1.2519x; 1.2519x over previous
#include <cuda_runtime.h>

#define BB 256
#define TT 2048
#define HH 128
#define FC1N 64
#define RING 32
#define RPAD 132    // ring row stride in floats

// dynamic SMEM layout (float offsets)
#define OFF_X     0                          // padded x: TT*4
#define OFF_RING  (TT * 4)                   // RING*RPAD
#define OFF_WC    (OFF_RING + RING * RPAD)   // [3][HH]
#define OFF_P     (OFF_WC + 3 * HH)          // [4][96]
#define OFF_BC    (OFF_P + 4 * 96)
#define SMEM_FLOATS (OFF_BC + 4)

__device__ __forceinline__ unsigned long long fma2(unsigned long long a,
                                                   unsigned long long b,
                                                   unsigned long long c) {
    unsigned long long d;
    asm("fma.rn.f32x2 %0, %1, %2, %3;" : "=l"(d) : "l"(a), "l"(b), "l"(c));
    return d;
}
__device__ __forceinline__ unsigned long long add2(unsigned long long a,
                                                   unsigned long long b) {
    unsigned long long d;
    asm("add.rn.f32x2 %0, %1, %2;" : "=l"(d) : "l"(a), "l"(b));
    return d;
}
__device__ __forceinline__ unsigned long long pack2(float lo, float hi) {
    unsigned long long d;
    asm("mov.b64 %0, {%1, %2};" : "=l"(d) : "f"(lo), "f"(hi));
    return d;
}
__device__ __forceinline__ float2 unpack2(unsigned long long v) {
    float2 r;
    asm("mov.b64 {%0, %1}, %2;" : "=f"(r.x), "=f"(r.y) : "l"(v));
    return r;
}
__device__ __forceinline__ float tanh_fast(float x) {
    float y;
    asm("tanh.approx.f32 %0, %1;" : "=f"(y) : "f"(x));
    return y;
}

__global__ __launch_bounds__(128, 2)
void rnn_stagger_kernel(const float* __restrict__ x,
                        const float* __restrict__ hidden,
                        const float* __restrict__ W_ih,
                        const float* __restrict__ W_hh,
                        const float* __restrict__ b_ih,
                        const float* __restrict__ b_hh,
                        const float* __restrict__ W_fc1,
                        const float* __restrict__ b_fc1,
                        const float* __restrict__ W_fc2,
                        const float* __restrict__ b_fc2,
                        float* __restrict__ out)
{
    extern __shared__ __align__(16) float sm[];
    float* xR   = sm + OFF_X;       // padded: 4 floats per timestep
    float* ring = sm + OFF_RING;
    float* wc   = sm + OFF_WC;
    float* pr   = sm + OFF_P;
    float* bc   = sm + OFF_BC;

    const int b = blockIdx.x;
    const int j = threadIdx.x;

    // ---- preload x[b] into padded SMEM (xR[t*4 + c], c<3) ----
    {
        const float4* g = (const float4*)(x + (size_t)b * TT * 3);
        #pragma unroll
        for (int i = 0; i < (TT * 3 / 4) / HH; i++) {    // 12 iters
            float4 v = g[i * HH + j];
            int idx = 4 * (i * HH + j);                  // global float index
            xR[(idx / 3) * 4 + idx % 3] = v.x; idx++;
            xR[(idx / 3) * 4 + idx % 3] = v.y; idx++;
            xR[(idx / 3) * 4 + idx % 3] = v.z; idx++;
            xR[(idx / 3) * 4 + idx % 3] = v.w;
        }
    }

    // ---- W_hh row j as packed f32x2 (128 regs) ----
    unsigned long long w[HH / 2];
    {
        const unsigned long long* wg = (const unsigned long long*)(W_hh + j * HH);
        #pragma unroll
        for (int i = 0; i < HH / 2; i++) w[i] = wg[i];
    }

    const float wih0 = W_ih[j * 3 + 0];
    const float wih1 = W_ih[j * 3 + 1];
    const float wih2 = W_ih[j * 3 + 2];
    const float bias = b_ih[j] + b_hh[j];

    // ---- collapsed FC head ----
    {
        float c0 = 0.f, c1 = 0.f, c2 = 0.f;
        #pragma unroll 4
        for (int f = 0; f < FC1N; f++) {
            float v = W_fc1[f * HH + j];
            c0 = fmaf(W_fc2[0 * FC1N + f], v, c0);
            c1 = fmaf(W_fc2[1 * FC1N + f], v, c1);
            c2 = fmaf(W_fc2[2 * FC1N + f], v, c2);
        }
        wc[0 * HH + j] = c0; wc[1 * HH + j] = c1; wc[2 * HH + j] = c2;
    }
    if (j < 3) {
        float s = 0.f;
        #pragma unroll 8
        for (int f = 0; f < FC1N; f++)
            s = fmaf(W_fc2[j * FC1N + f], b_fc1[f], s);
        bc[j] = s + b_fc2[j];
    }

    // initial hidden state in slot RING-1 (t = -1)
    ring[(RING - 1) * RPAD + j] = hidden[b * HH + j];
    __syncthreads();

    // ---- anti-phase stagger: odd CTAs burn ~256 cyc once ----
    if (b & 1) {
        float acc = bias;
        #pragma unroll
        for (int i = 0; i < 64; i++)
            acc = fmaf(acc, 1.0000001f, 1e-7f);   // 64-deep dependent chain
        pr[j] = acc;        // dead store; fully overwritten at first FC drain
    }

    const int kg = j >> 5;
    const int tl = j & 31;
    float* outb = out + (size_t)b * TT * 3;

    float hv = 0.f;

    for (int tc = 0; tc < TT / RING; tc++) {
        #pragma unroll 1
        for (int ts = 0; ts < RING; ts++) {
            const int t = tc * RING + ts;

            // x projection from padded SMEM (single LDS.128)
            const float4 xq = *(const float4*)(xR + 4 * t);
            float xp = fmaf(xq.z, wih2, fmaf(xq.y, wih1, fmaf(xq.x, wih0, bias)));

            // 128-wide dot; xp pre-folded into accumulator 0
            const ulonglong2* hp =
                (const ulonglong2*)(ring + ((ts - 1) & (RING - 1)) * RPAD);
            unsigned long long a0 = pack2(xp, 0.f);
            unsigned long long a1 = 0ull, a2 = 0ull, a3 = 0ull;
            #pragma unroll
            for (int i = 0; i < 16; i++) {
                ulonglong2 ha = hp[2 * i];
                ulonglong2 hb = hp[2 * i + 1];
                a0 = fma2(w[4 * i + 0], ha.x, a0);
                a1 = fma2(w[4 * i + 1], ha.y, a1);
                a2 = fma2(w[4 * i + 2], hb.x, a2);
                a3 = fma2(w[4 * i + 3], hb.y, a3);
            }
            unsigned long long s2 = add2(add2(a0, a1), add2(a2, a3));
            float2 f = unpack2(s2);

            hv = tanh_fast(f.x + f.y);
            ring[ts * RPAD + j] = hv;
            __syncthreads();
        }

        // ---- amortized FC drain (slots 0..31 -> 96 outputs) ----
        {
            const float4* w0 = (const float4*)(wc + 0 * HH + kg * 32);
            const float4* w1 = (const float4*)(wc + 1 * HH + kg * 32);
            const float4* w2 = (const float4*)(wc + 2 * HH + kg * 32);
            const float4* h4 = (const float4*)(ring + tl * RPAD + kg * 32);
            float p0 = 0.f, p1 = 0.f, p2 = 0.f;
            #pragma unroll
            for (int i = 0; i < 8; i++) {
                float4 v = h4[i];
                float4 u0 = w0[i], u1 = w1[i], u2 = w2[i];
                p0 = fmaf(v.x, u0.x, fmaf(v.y, u0.y, fmaf(v.z, u0.z, fmaf(v.w, u0.w, p0))));
                p1 = fmaf(v.x, u1.x, fmaf(v.y, u1.y, fmaf(v.z, u1.z, fmaf(v.w, u1.w, p1))));
                p2 = fmaf(v.x, u2.x, fmaf(v.y, u2.y, fmaf(v.z, u2.z, fmaf(v.w, u2.w, p2))));
            }
            pr[kg * 96 + tl * 3 + 0] = p0;
            pr[kg * 96 + tl * 3 + 1] = p1;
            pr[kg * 96 + tl * 3 + 2] = p2;
            __syncthreads();

            if (j < 96) {
                float v = pr[j] + pr[96 + j] + pr[192 + j] + pr[288 + j] + bc[j % 3];
                outb[(size_t)(tc * RING) * 3 + j] = v;
            }
        }
    }

    out[(size_t)BB * TT * 3 + b * HH + j] = hv;
}

extern "C" void kernel_launch(void* const* d_in, const int* in_sizes, int n_in,
                              void* d_out, int out_size) {
    const float* x      = (const float*)d_in[0];
    const float* hidden = (const float*)d_in[1];
    const float* W_ih   = (const float*)d_in[2];
    const float* W_hh   = (const float*)d_in[3];
    const float* b_ih   = (const float*)d_in[4];
    const float* b_hh   = (const float*)d_in[5];
    const float* W_fc1  = (const float*)d_in[6];
    const float* b_fc1  = (const float*)d_in[7];
    const float* W_fc2  = (const float*)d_in[8];
    const float* b_fc2  = (const float*)d_in[9];
    float* out = (float*)d_out;

    const int smem_bytes = SMEM_FLOATS * sizeof(float);
    static bool attr_set = false;
    if (!attr_set) {
        cudaFuncSetAttribute(rnn_stagger_kernel,
                             cudaFuncAttributeMaxDynamicSharedMemorySize,
                             smem_bytes);
        attr_set = true;
    }
    rnn_stagger_kernel<<<BB, HH, smem_bytes>>>(
        x, hidden, W_ih, W_hh, b_ih, b_hh,
        W_fc1, b_fc1, W_fc2, b_fc2, out);
}